// round 4
// baseline (speedup 1.0000x reference)
#include <cuda_runtime.h>
#include <cstdint>

#define NN 50000
#define DD 128
#define RR 8
#define NMAT 9
#define NSEG (RR * NN)          // 400000 segments: seg = rel*NN + dst
#define NBLK ((NSEG + 511) / 512)  // 782 scan blocks
#define SA 140                  // A-tile row stride in floats (conflict-free frag loads)

// ---- static device scratch ----
__device__ float g_h[(size_t)NN * DD];            // hidden layer (25.6 MB)
__device__ float g_wt[2 * NMAT * DD * DD];        // frag-packed tf32 weights
__device__ int   g_cnt[NSEG];
__device__ int   g_off[NSEG + 1];
__device__ int   g_work[NSEG];
__device__ int   g_bsum[NBLK];
__device__ int   g_csrc[600000 + 64];             // CSR src lists
__device__ int   g_flags[2];

// ================= helpers =================
__device__ __forceinline__ float to_tf32(float x) {
    float r;
    asm("cvt.rna.tf32.f32 %0, %1;" : "=f"(r) : "f"(x));
    return r;
}
__device__ __forceinline__ uint32_t smem_u32(const void* p) {
    uint32_t a;
    asm("{ .reg .u64 t; cvta.to.shared.u64 t, %1; cvt.u32.u64 %0, t; }" : "=r"(a) : "l"(p));
    return a;
}
__device__ __forceinline__ void cp_async16(uint32_t saddr, const void* gptr) {
    asm volatile("cp.async.cg.shared.global [%0], [%1], 16;"
                 :: "r"(saddr), "l"(__cvta_generic_to_global(gptr)) : "memory");
}
#define CP_COMMIT() asm volatile("cp.async.commit_group;" ::: "memory")
#define CP_WAIT0()  asm volatile("cp.async.wait_group 0;" ::: "memory")

__device__ __forceinline__ void mma_tf32(float* c, const uint4 a, const uint2 b) {
    asm volatile(
        "mma.sync.aligned.m16n8k8.row.col.f32.tf32.tf32.f32 "
        "{%0,%1,%2,%3}, {%4,%5,%6,%7}, {%8,%9}, {%0,%1,%2,%3};"
        : "+f"(c[0]), "+f"(c[1]), "+f"(c[2]), "+f"(c[3])
        : "r"(a.x), "r"(a.y), "r"(a.z), "r"(a.w), "r"(b.x), "r"(b.y));
}

__device__ __forceinline__ long long ld_idx(const void* p, long long i, int is64) {
    return is64 ? ((const long long*)p)[i] : (long long)((const int*)p)[i];
}

// ================= CSR build =================
__global__ void setup_kernel(const unsigned* __restrict__ ei,
                             const unsigned* __restrict__ et, int n) {
    int i = blockIdx.x * blockDim.x + threadIdx.x;
    if (i < n) g_cnt[i] = 0;
    if (blockIdx.x == 0 && threadIdx.x == 0) {
        unsigned a = 0, b = 0;
        for (int j = 1; j < 64; j += 2) { a |= ei[j]; b |= et[j]; }
        g_flags[0] = (a == 0) ? 1 : 0;
        g_flags[1] = (b == 0) ? 1 : 0;
    }
}

__global__ void count_kernel(const void* __restrict__ ei,
                             const void* __restrict__ et, int E) {
    int e = blockIdx.x * blockDim.x + threadIdx.x;
    if (e >= E) return;
    int dst = (int)ld_idx(ei, (long long)E + e, g_flags[0]);
    int rel = (int)ld_idx(et, e, g_flags[1]);
    atomicAdd(&g_cnt[rel * NN + dst], 1);
}

// per-block exclusive scan of g_cnt -> g_off (partial), block totals -> g_bsum
__global__ __launch_bounds__(512)
void scan1_kernel() {
    __shared__ int s[512];
    int tid = threadIdx.x;
    int idx = blockIdx.x * 512 + tid;
    int v = (idx < NSEG) ? g_cnt[idx] : 0;
    s[tid] = v;
    __syncthreads();
#pragma unroll
    for (int o = 1; o < 512; o <<= 1) {
        int t = (tid >= o) ? s[tid - o] : 0;
        __syncthreads();
        s[tid] += t;
        __syncthreads();
    }
    int incl = s[tid];
    if (idx < NSEG) g_off[idx] = incl - v;
    if (tid == 511) g_bsum[blockIdx.x] = incl;
}

// each block sums bsum[0..blk) (reduction) and adds base; writes final off + work
__global__ __launch_bounds__(512)
void scan2_kernel(int E) {
    __shared__ int red[512];
    int tid = threadIdx.x, blk = blockIdx.x;
    int acc = 0;
    for (int j = tid; j < blk; j += 512) acc += g_bsum[j];
    red[tid] = acc;
    __syncthreads();
#pragma unroll
    for (int o = 256; o > 0; o >>= 1) {
        if (tid < o) red[tid] += red[tid + o];
        __syncthreads();
    }
    int base = red[0];
    int idx = blk * 512 + tid;
    if (idx < NSEG) {
        int v = g_off[idx] + base;
        g_off[idx] = v;
        g_work[idx] = v;
    }
    if (blk == 0 && tid == 0) g_off[NSEG] = E;
}

__global__ void scatter_kernel(const void* __restrict__ ei,
                               const void* __restrict__ et, int E) {
    int e = blockIdx.x * blockDim.x + threadIdx.x;
    if (e >= E) return;
    int src = (int)ld_idx(ei, e, g_flags[0]);
    int dst = (int)ld_idx(ei, (long long)E + e, g_flags[0]);
    int rel = (int)ld_idx(et, e, g_flags[1]);
    int pos = atomicAdd(&g_work[rel * NN + dst], 1);
    g_csrc[pos] = src;
}

// weights -> tf32 fragment-packed (B frag of m16n8k8: lane=(n&7)*4+(k&3), slot=(k>>2)&1)
__global__ void wconv_kernel(const float* __restrict__ w1, const float* __restrict__ r1,
                             const float* __restrict__ w2, const float* __restrict__ r2) {
    int l = blockIdx.x / NMAT, m = blockIdx.x % NMAT;
    const float* src = (l == 0) ? (m < RR ? w1 + (size_t)m * DD * DD : r1)
                                : (m < RR ? w2 + (size_t)m * DD * DD : r2);
    float* dst = g_wt + (size_t)(l * NMAT + m) * DD * DD;
    for (int idx = threadIdx.x; idx < DD * DD; idx += blockDim.x) {
        int k = idx >> 7, n = idx & 127;
        float v = to_tf32(src[idx]);
        int kc = k >> 3, nt = n >> 3;
        int lane = (n & 7) * 4 + (k & 3);
        int slot = (k >> 2) & 1;
        dst[((kc * 16 + nt) * 32 + lane) * 2 + slot] = v;
    }
}

// ================= fused RGCN layer =================
// 391 CTAs x 256 thr. smem: Atile 128*SA floats | Btile 16384 floats
#define SM_A_BYTES (128 * SA * 4)
#define SM_B_OFF   SM_A_BYTES
#define SM_TOTAL   (SM_A_BYTES + 65536)

__global__ __launch_bounds__(256, 1)
void fused_layer(const float* __restrict__ Xopt, int layer,
                 const float* __restrict__ bias, float* __restrict__ dout) {
    extern __shared__ char smem[];
    float* At = (float*)smem;
    float* Bt = (float*)(smem + SM_B_OFF);
    uint32_t sb = smem_u32(smem);

    const float* X = Xopt ? Xopt : g_h;
    int tid = threadIdx.x;
    int lane = tid & 31, wid = tid >> 5;
    int wm = wid & 1, wn = wid >> 1;
    int n0 = blockIdx.x * 128;

    float acc[4][4][4];
#pragma unroll
    for (int i = 0; i < 4; i++)
#pragma unroll
        for (int j = 0; j < 4; j++)
#pragma unroll
            for (int q = 0; q < 4; q++) acc[i][j][q] = 0.f;

    for (int r = 0; r < NMAT; r++) {
        // async-stage B tile for this relation (overlaps with gather)
        {
            const char* bsrc = (const char*)(g_wt + (size_t)(layer * NMAT + r) * DD * DD);
#pragma unroll
            for (int j = 0; j < 16; j++)
                cp_async16(sb + SM_B_OFF + (j * 256 + tid) * 16, bsrc + (j * 256 + tid) * 16);
            CP_COMMIT();
        }

        if (r < RR) {
            // gather mean rows: warp owns rows wid*16 .. +15 ; dual-chain pipeline
            int rowbase = wid * 16;
            int seg0 = r * NN + n0 + rowbase;
            int offl = 0;
            {
                int idx = seg0 + lane;
                if (lane < 17 && idx <= NSEG) offl = g_off[idx];
            }
#pragma unroll
            for (int sp = 0; sp < 8; sp++) {
                int rA = rowbase + sp, rB = rowbase + sp + 8;
                int begA = __shfl_sync(0xffffffff, offl, sp);
                int endA = __shfl_sync(0xffffffff, offl, sp + 1);
                int begB = __shfl_sync(0xffffffff, offl, sp + 8);
                int endB = __shfl_sync(0xffffffff, offl, sp + 9);
                if (n0 + rA >= NN) { begA = 0; endA = 0; }
                if (n0 + rB >= NN) { begB = 0; endB = 0; }
                float sA = 1.0f / (float)max(endA - begA, 1);
                float sB = 1.0f / (float)max(endB - begB, 1);

                float4 aA = make_float4(0.f, 0.f, 0.f, 0.f);
                float4 aB = make_float4(0.f, 0.f, 0.f, 0.f);
                float4 vA = aA, vB = aB;
                bool hA = begA < endA, hB = begB < endB;
                if (hA) vA = *(const float4*)(X + (size_t)g_csrc[begA] * DD + lane * 4);
                if (hB) vB = *(const float4*)(X + (size_t)g_csrc[begB] * DD + lane * 4);
                while (hA || hB) {
                    int nA = begA + 1, nB = begB + 1;
                    float4 wA = vA, wB = vB;
                    bool hA2 = hA && (nA < endA);
                    bool hB2 = hB && (nB < endB);
                    if (hA2) wA = *(const float4*)(X + (size_t)g_csrc[nA] * DD + lane * 4);
                    if (hB2) wB = *(const float4*)(X + (size_t)g_csrc[nB] * DD + lane * 4);
                    if (hA) { aA.x += vA.x; aA.y += vA.y; aA.z += vA.z; aA.w += vA.w; }
                    if (hB) { aB.x += vB.x; aB.y += vB.y; aB.z += vB.z; aB.w += vB.w; }
                    vA = wA; vB = wB; begA = nA; begB = nB; hA = hA2; hB = hB2;
                }
                *(float4*)(At + rA * SA + lane * 4) =
                    make_float4(to_tf32(aA.x * sA), to_tf32(aA.y * sA),
                                to_tf32(aA.z * sA), to_tf32(aA.w * sA));
                *(float4*)(At + rB * SA + lane * 4) =
                    make_float4(to_tf32(aB.x * sB), to_tf32(aB.y * sB),
                                to_tf32(aB.z * sB), to_tf32(aB.w * sB));
            }
        } else {
            // root term: own rows
#pragma unroll
            for (int i = 0; i < 16; i++) {
                int row = (tid >> 1);
                int q = (tid & 1) * 16 + i;
                float4 v = make_float4(0.f, 0.f, 0.f, 0.f);
                if (n0 + row < NN)
                    v = *(const float4*)(X + (size_t)(n0 + row) * DD + q * 4);
                *(float4*)(At + row * SA + q * 4) =
                    make_float4(to_tf32(v.x), to_tf32(v.y), to_tf32(v.z), to_tf32(v.w));
            }
        }

        CP_WAIT0();
        __syncthreads();

        // 128x128x128 accumulate
#pragma unroll
        for (int kc = 0; kc < 16; kc++) {
            int c0 = kc * 8 + (lane & 3);
            uint4 aF[4];
            uint2 bF[4];
#pragma unroll
            for (int mf = 0; mf < 4; mf++) {
                int r0 = wm * 64 + mf * 16 + (lane >> 2);
                aF[mf].x = __float_as_uint(At[r0 * SA + c0]);
                aF[mf].y = __float_as_uint(At[(r0 + 8) * SA + c0]);
                aF[mf].z = __float_as_uint(At[r0 * SA + c0 + 4]);
                aF[mf].w = __float_as_uint(At[(r0 + 8) * SA + c0 + 4]);
            }
#pragma unroll
            for (int nf = 0; nf < 4; nf++)
                bF[nf] = *(const uint2*)(Bt + ((kc * 16 + wn * 4 + nf) * 32 + lane) * 2);
#pragma unroll
            for (int mf = 0; mf < 4; mf++)
#pragma unroll
                for (int nf = 0; nf < 4; nf++)
                    mma_tf32(acc[mf][nf], aF[mf], bF[nf]);
        }
        __syncthreads();   // protect At/Bt before next relation overwrites
    }

    // epilogue: bias + relu
    float* O = dout ? dout : g_h;
#pragma unroll
    for (int mf = 0; mf < 4; mf++) {
        int r0 = wm * 64 + mf * 16 + (lane >> 2);
#pragma unroll
        for (int nf = 0; nf < 4; nf++) {
            int col = wn * 32 + nf * 8 + 2 * (lane & 3);
#pragma unroll
            for (int h = 0; h < 2; h++) {
                int gr = n0 + r0 + h * 8;
                if (gr < NN) {
                    float v0 = fmaxf(acc[mf][nf][h * 2 + 0] + bias[col], 0.f);
                    float v1 = fmaxf(acc[mf][nf][h * 2 + 1] + bias[col + 1], 0.f);
                    *(float2*)(O + (size_t)gr * DD + col) = make_float2(v0, v1);
                }
            }
        }
    }
}

// =================================================================
extern "C" void kernel_launch(void* const* d_in, const int* in_sizes, int n_in,
                              void* d_out, int out_size) {
    const float* x     = (const float*)d_in[0];
    const void*  ei    = d_in[1];
    const void*  et    = d_in[2];
    const float* w1    = (const float*)d_in[3];
    const float* root1 = (const float*)d_in[4];
    const float* b1    = (const float*)d_in[5];
    const float* w2    = (const float*)d_in[6];
    const float* root2 = (const float*)d_in[7];
    const float* b2    = (const float*)d_in[8];
    float* out = (float*)d_out;

    int E = in_sizes[2];

    cudaFuncSetAttribute(fused_layer, cudaFuncAttributeMaxDynamicSharedMemorySize, SM_TOTAL);

    setup_kernel<<<(NSEG + 255) / 256, 256>>>((const unsigned*)ei, (const unsigned*)et, NSEG);
    count_kernel<<<(E + 255) / 256, 256>>>(ei, et, E);
    scan1_kernel<<<NBLK, 512>>>();
    scan2_kernel<<<NBLK, 512>>>(E);
    scatter_kernel<<<(E + 255) / 256, 256>>>(ei, et, E);
    wconv_kernel<<<2 * NMAT, 256>>>(w1, root1, w2, root2);

    fused_layer<<<391, 256, SM_TOTAL>>>(x, 0, b1, nullptr);    // layer 1 -> g_h
    fused_layer<<<391, 256, SM_TOTAL>>>(nullptr, 1, b2, out);  // layer 2 -> out
}

// round 10
// speedup vs baseline: 1.0411x; 1.0411x over previous
#include <cuda_runtime.h>
#include <cstdint>

#define NN 50000
#define DD 128
#define RR 8
#define NMAT 9
#define NSEG (RR * NN)             // 400000 segments: seg = rel*NN + dst
#define NBLK ((NSEG + 511) / 512)  // 782 scan blocks
#define SA 140                     // A-tile row stride (conflict-free frag loads)

// ---- static device scratch ----
__device__ float g_h[(size_t)NN * DD];            // hidden layer (25.6 MB)
__device__ float g_wt[2 * NMAT * DD * DD];        // frag-packed tf32 weights
__device__ int   g_cnt[NSEG];                     // zero-initialized; re-zeroed by scan1
__device__ int   g_off[NSEG + 1];
__device__ int   g_work[NSEG];
__device__ int   g_bsum[NBLK];
__device__ int   g_csrc[600000 + 64];             // CSR src lists

// ================= helpers =================
__device__ __forceinline__ float to_tf32(float x) {
    float r;
    asm("cvt.rna.tf32.f32 %0, %1;" : "=f"(r) : "f"(x));
    return r;
}
__device__ __forceinline__ uint32_t smem_u32(const void* p) {
    uint32_t a;
    asm("{ .reg .u64 t; cvta.to.shared.u64 t, %1; cvt.u32.u64 %0, t; }" : "=r"(a) : "l"(p));
    return a;
}
__device__ __forceinline__ void cp_async16(uint32_t saddr, const void* gptr) {
    asm volatile("cp.async.cg.shared.global [%0], [%1], 16;"
                 :: "r"(saddr), "l"(__cvta_generic_to_global(gptr)) : "memory");
}
#define CP_COMMIT() asm volatile("cp.async.commit_group;" ::: "memory")
#define CP_WAIT0()  asm volatile("cp.async.wait_group 0;" ::: "memory")

__device__ __forceinline__ void mma_tf32(float* c, const uint4 a, const uint2 b) {
    asm volatile(
        "mma.sync.aligned.m16n8k8.row.col.f32.tf32.tf32.f32 "
        "{%0,%1,%2,%3}, {%4,%5,%6,%7}, {%8,%9}, {%0,%1,%2,%3};"
        : "+f"(c[0]), "+f"(c[1]), "+f"(c[2]), "+f"(c[3])
        : "r"(a.x), "r"(a.y), "r"(a.z), "r"(a.w), "r"(b.x), "r"(b.y));
}

__device__ __forceinline__ long long ld_idx(const void* p, long long i, int is64) {
    return is64 ? ((const long long*)p)[i] : (long long)((const int*)p)[i];
}

// block-local dtype detect: int64 little-endian node/rel ids < 2^31 have all
// odd 32-bit words zero; random int32 ids cannot produce that pattern.
__device__ __forceinline__ void local_detect(const unsigned* ei, const unsigned* et,
                                             int* f0, int* f1) {
    __shared__ int s0, s1;
    if (threadIdx.x == 0) {
        unsigned a = 0, b = 0;
        for (int j = 1; j < 64; j += 2) { a |= ei[j]; b |= et[j]; }
        s0 = (a == 0) ? 1 : 0;
        s1 = (b == 0) ? 1 : 0;
    }
    __syncthreads();
    *f0 = s0; *f1 = s1;
}

// ================= CSR build =================
__global__ void count_kernel(const unsigned* __restrict__ ei,
                             const unsigned* __restrict__ et, int E) {
    int f0, f1;
    local_detect(ei, et, &f0, &f1);
    int e = blockIdx.x * blockDim.x + threadIdx.x;
    if (e >= E) return;
    int dst = (int)ld_idx(ei, (long long)E + e, f0);
    int rel = (int)ld_idx(et, e, f1);
    atomicAdd(&g_cnt[rel * NN + dst], 1);
}

// per-block exclusive scan of g_cnt -> g_off (partial); zero g_cnt for next replay
__global__ __launch_bounds__(512)
void scan1_kernel() {
    __shared__ int s[512];
    int tid = threadIdx.x;
    int idx = blockIdx.x * 512 + tid;
    int v = 0;
    if (idx < NSEG) { v = g_cnt[idx]; g_cnt[idx] = 0; }
    s[tid] = v;
    __syncthreads();
#pragma unroll
    for (int o = 1; o < 512; o <<= 1) {
        int t = (tid >= o) ? s[tid - o] : 0;
        __syncthreads();
        s[tid] += t;
        __syncthreads();
    }
    int incl = s[tid];
    if (idx < NSEG) g_off[idx] = incl - v;
    if (tid == 511) g_bsum[blockIdx.x] = incl;
}

__global__ __launch_bounds__(512)
void scan2_kernel(int E) {
    __shared__ int red[512];
    int tid = threadIdx.x, blk = blockIdx.x;
    int acc = 0;
    for (int j = tid; j < blk; j += 512) acc += g_bsum[j];
    red[tid] = acc;
    __syncthreads();
#pragma unroll
    for (int o = 256; o > 0; o >>= 1) {
        if (tid < o) red[tid] += red[tid + o];
        __syncthreads();
    }
    int base = red[0];
    int idx = blk * 512 + tid;
    if (idx < NSEG) {
        int v = g_off[idx] + base;
        g_off[idx] = v;
        g_work[idx] = v;
    }
    if (blk == 0 && tid == 0) g_off[NSEG] = E;
}

__global__ void scatter_kernel(const unsigned* __restrict__ ei,
                               const unsigned* __restrict__ et, int E) {
    int f0, f1;
    local_detect(ei, et, &f0, &f1);
    int e = blockIdx.x * blockDim.x + threadIdx.x;
    if (e >= E) return;
    int src = (int)ld_idx(ei, e, f0);
    int dst = (int)ld_idx(ei, (long long)E + e, f0);
    int rel = (int)ld_idx(et, e, f1);
    int pos = atomicAdd(&g_work[rel * NN + dst], 1);
    g_csrc[pos] = src;
}

// weights -> tf32 fragment-packed (B frag of m16n8k8: lane=(n&7)*4+(k&3), slot=(k>>2)&1)
__global__ void wconv_kernel(const float* __restrict__ w1, const float* __restrict__ r1,
                             const float* __restrict__ w2, const float* __restrict__ r2) {
    int l = blockIdx.x / NMAT, m = blockIdx.x % NMAT;
    const float* src = (l == 0) ? (m < RR ? w1 + (size_t)m * DD * DD : r1)
                                : (m < RR ? w2 + (size_t)m * DD * DD : r2);
    float* dst = g_wt + (size_t)(l * NMAT + m) * DD * DD;
    for (int idx = threadIdx.x; idx < DD * DD; idx += blockDim.x) {
        int k = idx >> 7, n = idx & 127;
        float v = to_tf32(src[idx]);
        int kc = k >> 3, nt = n >> 3;
        int lane = (n & 7) * 4 + (k & 3);
        int slot = (k >> 2) & 1;
        dst[((kc * 16 + nt) * 32 + lane) * 2 + slot] = v;
    }
}

// ================= fused RGCN layer =================
#define SM_A_BYTES (128 * SA * 4)
#define SM_B_OFF   SM_A_BYTES
#define SM_TOTAL   (SM_A_BYTES + 65536)

#define FLUSH_ROW(rowloc)                                                          \
    do {                                                                           \
        int _b = __shfl_sync(0xffffffffu, offl, (rowloc));                         \
        int _e = __shfl_sync(0xffffffffu, offl, (rowloc) + 1);                     \
        float _sc = __fdividef(1.0f, (float)(_e - _b));                            \
        *(float4*)(At + (rowbase + (rowloc)) * SA + lane * 4) =                    \
            make_float4(to_tf32(acc.x * _sc), to_tf32(acc.y * _sc),                \
                        to_tf32(acc.z * _sc), to_tf32(acc.w * _sc));               \
    } while (0)

__global__ __launch_bounds__(256, 1)
void fused_layer(const float* __restrict__ Xopt, int layer,
                 const float* __restrict__ bias, float* __restrict__ dout) {
    extern __shared__ char smem[];
    float* At = (float*)smem;
    float* Bt = (float*)(smem + SM_B_OFF);
    uint32_t sb = smem_u32(smem);

    const float* X = Xopt ? Xopt : g_h;
    int tid = threadIdx.x;
    int lane = tid & 31, wid = tid >> 5;
    int wm = wid & 1, wn = wid >> 1;
    int n0 = blockIdx.x * 128;

    float accm[4][4][4];
#pragma unroll
    for (int i = 0; i < 4; i++)
#pragma unroll
        for (int j = 0; j < 4; j++)
#pragma unroll
            for (int q = 0; q < 4; q++) accm[i][j][q] = 0.f;

    for (int r = 0; r < NMAT; r++) {
        // async-stage B tile for this relation (overlaps with gather)
        {
            const char* bsrc = (const char*)(g_wt + (size_t)(layer * NMAT + r) * DD * DD);
#pragma unroll
            for (int j = 0; j < 16; j++)
                cp_async16(sb + SM_B_OFF + (j * 256 + tid) * 16, bsrc + (j * 256 + tid) * 16);
            CP_COMMIT();
        }

        if (r < RR) {
            int rowbase = wid * 16;
            // warp-local CSR offsets for its 16 rows (clamped at NN boundary)
            int offl = 0;
            {
                int node = n0 + rowbase + lane;
                if (node > NN) node = NN;
                if (lane < 17) offl = g_off[r * NN + node];
            }
            // zero own rows
#pragma unroll
            for (int i = 0; i < 16; i++)
                *(float4*)(At + (rowbase + i) * SA + lane * 4) =
                    make_float4(0.f, 0.f, 0.f, 0.f);

            int beg = __shfl_sync(0xffffffffu, offl, 0);
            int end = __shfl_sync(0xffffffffu, offl, 16);
            int nE = end - beg;

            int cur = 0, have = 0;
            int nxtb = __shfl_sync(0xffffffffu, offl, 1) - beg;  // boundary of row cur
            float4 acc = make_float4(0.f, 0.f, 0.f, 0.f);

            for (int base = 0; base < nE; base += 32) {
                int m = min(32, nE - base);
                int sidx = 0;
                if (lane < m) sidx = g_csrc[beg + base + lane];   // coalesced idx batch

                // depth-3 pipelined row loads
                float4 v0 = make_float4(0.f, 0.f, 0.f, 0.f), v1 = v0, v2 = v0;
                {
                    int s = __shfl_sync(0xffffffffu, sidx, 0);
                    v0 = *(const float4*)(X + (size_t)s * DD + lane * 4);
                    if (1 < m) {
                        s = __shfl_sync(0xffffffffu, sidx, 1);
                        v1 = *(const float4*)(X + (size_t)s * DD + lane * 4);
                    }
                    if (2 < m) {
                        s = __shfl_sync(0xffffffffu, sidx, 2);
                        v2 = *(const float4*)(X + (size_t)s * DD + lane * 4);
                    }
                }
                for (int j = 0; j < m; j++) {
                    float4 v = v0;
                    v0 = v1; v1 = v2;
                    if (j + 3 < m) {
                        int s = __shfl_sync(0xffffffffu, sidx, j + 3);
                        v2 = *(const float4*)(X + (size_t)s * DD + lane * 4);
                    }
                    int epos = base + j;
                    while (cur < 15 && epos >= nxtb) {
                        if (have) {
                            FLUSH_ROW(cur);
                            have = 0;
                            acc = make_float4(0.f, 0.f, 0.f, 0.f);
                        }
                        cur++;
                        nxtb = __shfl_sync(0xffffffffu, offl, cur + 1) - beg;
                    }
                    acc.x += v.x; acc.y += v.y; acc.z += v.z; acc.w += v.w;
                    have = 1;
                }
            }
            if (have) FLUSH_ROW(cur);
        } else {
            // root term: copy own rows (tf32-rounded)
#pragma unroll
            for (int i = 0; i < 16; i++) {
                int row = (tid >> 1);
                int q = (tid & 1) * 16 + i;
                float4 v = make_float4(0.f, 0.f, 0.f, 0.f);
                if (n0 + row < NN)
                    v = *(const float4*)(X + (size_t)(n0 + row) * DD + q * 4);
                *(float4*)(At + row * SA + q * 4) =
                    make_float4(to_tf32(v.x), to_tf32(v.y), to_tf32(v.z), to_tf32(v.w));
            }
        }

        CP_WAIT0();
        __syncthreads();

        // 128x128x128 accumulate
#pragma unroll
        for (int kc = 0; kc < 16; kc++) {
            int c0 = kc * 8 + (lane & 3);
            uint4 aF[4];
            uint2 bF[4];
#pragma unroll
            for (int mf = 0; mf < 4; mf++) {
                int r0 = wm * 64 + mf * 16 + (lane >> 2);
                aF[mf].x = __float_as_uint(At[r0 * SA + c0]);
                aF[mf].y = __float_as_uint(At[(r0 + 8) * SA + c0]);
                aF[mf].z = __float_as_uint(At[r0 * SA + c0 + 4]);
                aF[mf].w = __float_as_uint(At[(r0 + 8) * SA + c0 + 4]);
            }
#pragma unroll
            for (int nf = 0; nf < 4; nf++)
                bF[nf] = *(const uint2*)(Bt + ((kc * 16 + wn * 4 + nf) * 32 + lane) * 2);
#pragma unroll
            for (int mf = 0; mf < 4; mf++)
#pragma unroll
                for (int nf = 0; nf < 4; nf++)
                    mma_tf32(accm[mf][nf], aF[mf], bF[nf]);
        }
        __syncthreads();   // protect At/Bt before next relation overwrites
    }

    // epilogue: bias + relu
    float* O = dout ? dout : g_h;
#pragma unroll
    for (int mf = 0; mf < 4; mf++) {
        int r0 = wm * 64 + mf * 16 + (lane >> 2);
#pragma unroll
        for (int nf = 0; nf < 4; nf++) {
            int col = wn * 32 + nf * 8 + 2 * (lane & 3);
#pragma unroll
            for (int h = 0; h < 2; h++) {
                int gr = n0 + r0 + h * 8;
                if (gr < NN) {
                    float v0 = fmaxf(accm[mf][nf][h * 2 + 0] + bias[col], 0.f);
                    float v1 = fmaxf(accm[mf][nf][h * 2 + 1] + bias[col + 1], 0.f);
                    *(float2*)(O + (size_t)gr * DD + col) = make_float2(v0, v1);
                }
            }
        }
    }
}

// =================================================================
extern "C" void kernel_launch(void* const* d_in, const int* in_sizes, int n_in,
                              void* d_out, int out_size) {
    const float* x     = (const float*)d_in[0];
    const unsigned* ei = (const unsigned*)d_in[1];
    const unsigned* et = (const unsigned*)d_in[2];
    const float* w1    = (const float*)d_in[3];
    const float* root1 = (const float*)d_in[4];
    const float* b1    = (const float*)d_in[5];
    const float* w2    = (const float*)d_in[6];
    const float* root2 = (const float*)d_in[7];
    const float* b2    = (const float*)d_in[8];
    float* out = (float*)d_out;

    int E = in_sizes[2];

    cudaFuncSetAttribute(fused_layer, cudaFuncAttributeMaxDynamicSharedMemorySize, SM_TOTAL);

    count_kernel<<<(E + 255) / 256, 256>>>(ei, et, E);          // 0
    wconv_kernel<<<2 * NMAT, 256>>>(w1, root1, w2, root2);      // 1
    scan1_kernel<<<NBLK, 512>>>();                              // 2
    scan2_kernel<<<NBLK, 512>>>(E);                             // 3
    scatter_kernel<<<(E + 255) / 256, 256>>>(ei, et, E);        // 4

    fused_layer<<<391, 256, SM_TOTAL>>>(x, 0, b1, nullptr);     // 5 <- ncu
    fused_layer<<<391, 256, SM_TOTAL>>>(nullptr, 1, b2, out);   // 6
}

// round 13
// speedup vs baseline: 1.3559x; 1.3023x over previous
#include <cuda_runtime.h>
#include <cstdint>

#define NN 50000
#define DD 128
#define RR 8
#define NMAT 9
#define NSEG (RR * NN)             // 400000 segments: seg = rel*NN + dst
#define NBLK ((NSEG + 511) / 512)  // 782 scan tiles
#define SA 132                     // A-tile row stride (conflict-free frag loads)

// ---- static device scratch ----
__device__ float g_h[(size_t)NN * DD];            // hidden layer (25.6 MB)
__device__ float g_wt[2 * NMAT * DD * DD];        // frag-packed tf32 weights
__device__ int   g_cnt[NSEG];                     // zero-init; re-zeroed by scan
__device__ int   g_off[NSEG + 1];
__device__ int   g_work[NSEG];
__device__ int   g_csrc[600000 + 64];             // CSR src lists
__device__ unsigned long long g_tstat[NBLK];      // lookback scan tile status
__device__ int   g_tilectr;

// ================= helpers =================
__device__ __forceinline__ float to_tf32(float x) {
    float r;
    asm("cvt.rna.tf32.f32 %0, %1;" : "=f"(r) : "f"(x));
    return r;
}
__device__ __forceinline__ void mma_tf32(float* c, const uint4 a, const uint2 b) {
    asm volatile(
        "mma.sync.aligned.m16n8k8.row.col.f32.tf32.tf32.f32 "
        "{%0,%1,%2,%3}, {%4,%5,%6,%7}, {%8,%9}, {%0,%1,%2,%3};"
        : "+f"(c[0]), "+f"(c[1]), "+f"(c[2]), "+f"(c[3])
        : "r"(a.x), "r"(a.y), "r"(a.z), "r"(a.w), "r"(b.x), "r"(b.y));
}
__device__ __forceinline__ long long ld_idx(const void* p, long long i, int is64) {
    return is64 ? ((const long long*)p)[i] : (long long)((const int*)p)[i];
}
// block-local dtype detect: int64 little-endian ids < 2^31 have all odd
// 32-bit words zero; random int32 ids cannot produce that pattern.
__device__ __forceinline__ void local_detect(const unsigned* ei, const unsigned* et,
                                             int* f0, int* f1) {
    __shared__ int s0, s1;
    if (threadIdx.x == 0) {
        unsigned a = 0, b = 0;
        for (int j = 1; j < 64; j += 2) { a |= ei[j]; b |= et[j]; }
        s0 = (a == 0) ? 1 : 0;
        s1 = (b == 0) ? 1 : 0;
    }
    __syncthreads();
    *f0 = s0; *f1 = s1;
}

// ========== launch 0: edge count + weight pack + scan-state reset ==========
// blocks [0, EB): count edges.  blocks [EB, EB+18): pack one weight matrix.
__global__ void countw_kernel(const unsigned* __restrict__ ei,
                              const unsigned* __restrict__ et, int E, int EB,
                              const float* __restrict__ w1, const float* __restrict__ r1,
                              const float* __restrict__ w2, const float* __restrict__ r2) {
    int b = blockIdx.x;
    int tid = threadIdx.x;
    if (b < EB) {
        int f0, f1;
        local_detect(ei, et, &f0, &f1);
        if (b == 0) {
            for (int i = tid; i < NBLK; i += 256) g_tstat[i] = 0ULL;
            if (tid == 0) g_tilectr = 0;
        }
        int e = b * 256 + tid;
        if (e >= E) return;
        int dst = (int)ld_idx(ei, (long long)E + e, f0);
        int rel = (int)ld_idx(et, e, f1);
        atomicAdd(&g_cnt[rel * NN + dst], 1);
    } else {
        int b2 = b - EB;               // 0..17
        int l = b2 / NMAT, m = b2 % NMAT;
        const float* src = (l == 0) ? (m < RR ? w1 + (size_t)m * DD * DD : r1)
                                    : (m < RR ? w2 + (size_t)m * DD * DD : r2);
        float* dst = g_wt + (size_t)(l * NMAT + m) * DD * DD;
        for (int idx = tid; idx < DD * DD; idx += 256) {
            int k = idx >> 7, n = idx & 127;
            float v = to_tf32(src[idx]);
            int kc = k >> 3, nt = n >> 3;
            int lane = (n & 7) * 4 + (k & 3);
            int slot = (k >> 2) & 1;
            dst[((kc * 16 + nt) * 32 + lane) * 2 + slot] = v;
        }
    }
}

// ========== launch 1: single-pass exclusive scan (decoupled lookback) ==========
#define FLAG_AGG (1ULL << 62)
#define FLAG_PFX (2ULL << 62)
#define VAL_MASK ((1ULL << 62) - 1)

__global__ __launch_bounds__(512)
void scan_kernel(int E) {
    __shared__ int s[512];
    __shared__ int s_tile, s_base;
    int tid = threadIdx.x;
    if (tid == 0) s_tile = atomicAdd(&g_tilectr, 1);
    __syncthreads();
    int tile = s_tile;
    int idx = tile * 512 + tid;

    int v = 0;
    if (idx < NSEG) { v = g_cnt[idx]; g_cnt[idx] = 0; }
    s[tid] = v;
    __syncthreads();
#pragma unroll
    for (int o = 1; o < 512; o <<= 1) {
        int t = (tid >= o) ? s[tid - o] : 0;
        __syncthreads();
        s[tid] += t;
        __syncthreads();
    }
    int incl = s[tid];
    int total = s[511];

    if (tid == 0) {
        if (tile == 0) {
            atomicExch(&g_tstat[0], FLAG_PFX | (unsigned long long)total);
            s_base = 0;
        } else {
            atomicExch(&g_tstat[tile], FLAG_AGG | (unsigned long long)total);
            long long run = 0;
            int t = tile - 1;
            while (true) {
                unsigned long long st;
                do { st = atomicAdd(&g_tstat[t], 0ULL); } while ((st >> 62) == 0);
                run += (long long)(st & VAL_MASK);
                if ((st >> 62) == 2) break;
                t--;
            }
            atomicExch(&g_tstat[tile],
                       FLAG_PFX | (unsigned long long)(run + (long long)total));
            s_base = (int)run;
        }
    }
    __syncthreads();
    int base = s_base;
    if (idx < NSEG) {
        int o = base + incl - v;
        g_off[idx] = o;
        g_work[idx] = o;
    }
    if (tile == NBLK - 1 && tid == 0) g_off[NSEG] = E;
}

// ========== launch 2: scatter ==========
__global__ void scatter_kernel(const unsigned* __restrict__ ei,
                               const unsigned* __restrict__ et, int E) {
    int f0, f1;
    local_detect(ei, et, &f0, &f1);
    int e = blockIdx.x * blockDim.x + threadIdx.x;
    if (e >= E) return;
    int src = (int)ld_idx(ei, e, f0);
    int dst = (int)ld_idx(ei, (long long)E + e, f0);
    int rel = (int)ld_idx(et, e, f1);
    int pos = atomicAdd(&g_work[rel * NN + dst], 1);
    g_csrc[pos] = src;
}

// ========== launches 3,4: fused RGCN layer ==========
// smem = A tile only (128 x SA floats = 67.6 KB) -> 2 CTAs/SM; B frags via LDG
#define SM_TOTAL (128 * SA * 4)

#define FLUSH_ROW(rowloc)                                                          \
    do {                                                                           \
        int _b = __shfl_sync(0xffffffffu, offl, (rowloc));                         \
        int _e = __shfl_sync(0xffffffffu, offl, (rowloc) + 1);                     \
        float _sc = __fdividef(1.0f, (float)(_e - _b));                            \
        *(float4*)(At + (rowbase + (rowloc)) * SA + lane * 4) =                    \
            make_float4(to_tf32(acc.x * _sc), to_tf32(acc.y * _sc),                \
                        to_tf32(acc.z * _sc), to_tf32(acc.w * _sc));               \
    } while (0)

__global__ __launch_bounds__(256, 2)
void fused_layer(const float* __restrict__ Xopt, int layer,
                 const float* __restrict__ bias, float* __restrict__ dout) {
    extern __shared__ char smem[];
    float* At = (float*)smem;

    const float* X = Xopt ? Xopt : g_h;
    int tid = threadIdx.x;
    int lane = tid & 31, wid = tid >> 5;
    int wm = wid & 1, wn = wid >> 1;
    int n0 = blockIdx.x * 128;

    float accm[4][4][4];
#pragma unroll
    for (int i = 0; i < 4; i++)
#pragma unroll
        for (int j = 0; j < 4; j++)
#pragma unroll
            for (int q = 0; q < 4; q++) accm[i][j][q] = 0.f;

    for (int r = 0; r < NMAT; r++) {
        if (r < RR) {
            int rowbase = wid * 16;
            int offl = 0;
            {
                int node = n0 + rowbase + lane;
                if (node > NN) node = NN;
                if (lane < 17) offl = g_off[r * NN + node];
            }
#pragma unroll
            for (int i = 0; i < 16; i++)
                *(float4*)(At + (rowbase + i) * SA + lane * 4) =
                    make_float4(0.f, 0.f, 0.f, 0.f);

            int beg = __shfl_sync(0xffffffffu, offl, 0);
            int end = __shfl_sync(0xffffffffu, offl, 16);
            int nE = end - beg;

            int cur = 0, have = 0;
            int nxtb = __shfl_sync(0xffffffffu, offl, 1) - beg;
            float4 acc = make_float4(0.f, 0.f, 0.f, 0.f);

            for (int base = 0; base < nE; base += 32) {
                int m = min(32, nE - base);
                int sidx = 0;
                if (lane < m) sidx = g_csrc[beg + base + lane];

                float4 v0 = make_float4(0.f, 0.f, 0.f, 0.f), v1 = v0, v2 = v0;
                {
                    int s = __shfl_sync(0xffffffffu, sidx, 0);
                    v0 = *(const float4*)(X + (size_t)s * DD + lane * 4);
                    if (1 < m) {
                        s = __shfl_sync(0xffffffffu, sidx, 1);
                        v1 = *(const float4*)(X + (size_t)s * DD + lane * 4);
                    }
                    if (2 < m) {
                        s = __shfl_sync(0xffffffffu, sidx, 2);
                        v2 = *(const float4*)(X + (size_t)s * DD + lane * 4);
                    }
                }
                for (int j = 0; j < m; j++) {
                    float4 v = v0;
                    v0 = v1; v1 = v2;
                    if (j + 3 < m) {
                        int s = __shfl_sync(0xffffffffu, sidx, j + 3);
                        v2 = *(const float4*)(X + (size_t)s * DD + lane * 4);
                    }
                    int epos = base + j;
                    while (cur < 15 && epos >= nxtb) {
                        if (have) {
                            FLUSH_ROW(cur);
                            have = 0;
                            acc = make_float4(0.f, 0.f, 0.f, 0.f);
                        }
                        cur++;
                        nxtb = __shfl_sync(0xffffffffu, offl, cur + 1) - beg;
                    }
                    acc.x += v.x; acc.y += v.y; acc.z += v.z; acc.w += v.w;
                    have = 1;
                }
            }
            if (have) FLUSH_ROW(cur);
        } else {
            // root term: copy own rows (tf32-rounded)
#pragma unroll
            for (int i = 0; i < 16; i++) {
                int row = (tid >> 1);
                int q = (tid & 1) * 16 + i;
                float4 v = make_float4(0.f, 0.f, 0.f, 0.f);
                if (n0 + row < NN)
                    v = *(const float4*)(X + (size_t)(n0 + row) * DD + q * 4);
                *(float4*)(At + row * SA + q * 4) =
                    make_float4(to_tf32(v.x), to_tf32(v.y), to_tf32(v.z), to_tf32(v.w));
            }
        }

        __syncthreads();   // At ready

        // 128x128x128 accumulate; B frags straight from L1/L2-resident g_wt
        const float* Bw = g_wt + (size_t)(layer * NMAT + r) * DD * DD;
#pragma unroll
        for (int kc = 0; kc < 16; kc++) {
            int c0 = kc * 8 + (lane & 3);
            uint4 aF[4];
            uint2 bF[4];
#pragma unroll
            for (int nf = 0; nf < 4; nf++)
                bF[nf] = *(const uint2*)(Bw + ((kc * 16 + wn * 4 + nf) * 32 + lane) * 2);
#pragma unroll
            for (int mf = 0; mf < 4; mf++) {
                int r0 = wm * 64 + mf * 16 + (lane >> 2);
                aF[mf].x = __float_as_uint(At[r0 * SA + c0]);
                aF[mf].y = __float_as_uint(At[(r0 + 8) * SA + c0]);
                aF[mf].z = __float_as_uint(At[r0 * SA + c0 + 4]);
                aF[mf].w = __float_as_uint(At[(r0 + 8) * SA + c0 + 4]);
            }
#pragma unroll
            for (int mf = 0; mf < 4; mf++)
#pragma unroll
                for (int nf = 0; nf < 4; nf++)
                    mma_tf32(accm[mf][nf], aF[mf], bF[nf]);
        }
        __syncthreads();   // protect At before next relation overwrites
    }

    // epilogue: bias + relu
    float* O = dout ? dout : g_h;
#pragma unroll
    for (int mf = 0; mf < 4; mf++) {
        int r0 = wm * 64 + mf * 16 + (lane >> 2);
#pragma unroll
        for (int nf = 0; nf < 4; nf++) {
            int col = wn * 32 + nf * 8 + 2 * (lane & 3);
#pragma unroll
            for (int h = 0; h < 2; h++) {
                int gr = n0 + r0 + h * 8;
                if (gr < NN) {
                    float v0 = fmaxf(accm[mf][nf][h * 2 + 0] + bias[col], 0.f);
                    float v1 = fmaxf(accm[mf][nf][h * 2 + 1] + bias[col + 1], 0.f);
                    *(float2*)(O + (size_t)gr * DD + col) = make_float2(v0, v1);
                }
            }
        }
    }
}

// =================================================================
extern "C" void kernel_launch(void* const* d_in, const int* in_sizes, int n_in,
                              void* d_out, int out_size) {
    const float* x     = (const float*)d_in[0];
    const unsigned* ei = (const unsigned*)d_in[1];
    const unsigned* et = (const unsigned*)d_in[2];
    const float* w1    = (const float*)d_in[3];
    const float* root1 = (const float*)d_in[4];
    const float* b1    = (const float*)d_in[5];
    const float* w2    = (const float*)d_in[6];
    const float* root2 = (const float*)d_in[7];
    const float* b2    = (const float*)d_in[8];
    float* out = (float*)d_out;

    int E = in_sizes[2];
    int EB = (E + 255) / 256;

    cudaFuncSetAttribute(fused_layer, cudaFuncAttributeMaxDynamicSharedMemorySize, SM_TOTAL);

    countw_kernel<<<EB + 2 * NMAT, 256>>>(ei, et, E, EB, w1, root1, w2, root2); // 0
    scan_kernel<<<NBLK, 512>>>(E);                                              // 1
    scatter_kernel<<<EB, 256>>>(ei, et, E);                                     // 2

    fused_layer<<<391, 256, SM_TOTAL>>>(x, 0, b1, nullptr);     // 3 <- ncu capture
    fused_layer<<<391, 256, SM_TOTAL>>>(nullptr, 1, b2, out);   // 4
}

// round 14
// speedup vs baseline: 1.4379x; 1.0605x over previous
#include <cuda_runtime.h>
#include <cstdint>

#define NN 50000
#define DD 128
#define RR 8
#define NMAT 9
#define NSEG (RR * NN)             // 400000 segments: seg = rel*NN + dst
#define NBLK ((NSEG + 511) / 512)  // 782 scan tiles
#define SA 132                     // A-tile row stride (conflict-free frag loads)

// ---- static device scratch ----
__device__ float g_h[(size_t)NN * DD];            // hidden layer (25.6 MB)
__device__ float g_wt[2 * NMAT * DD * DD];        // frag-packed tf32 weights
__device__ int   g_cnt[NSEG];                     // zero-init; re-zeroed by scan
__device__ int   g_off[NSEG + 1];
__device__ int   g_work[NSEG];
__device__ int   g_csrc[600000 + 64];             // CSR src lists
__device__ unsigned long long g_tstat[NBLK];      // lookback scan tile status
__device__ int   g_tilectr;

// ================= helpers =================
__device__ __forceinline__ float to_tf32(float x) {
    float r;
    asm("cvt.rna.tf32.f32 %0, %1;" : "=f"(r) : "f"(x));
    return r;
}
__device__ __forceinline__ void mma_tf32(float* c, const uint4 a, const uint2 b) {
    asm volatile(
        "mma.sync.aligned.m16n8k8.row.col.f32.tf32.tf32.f32 "
        "{%0,%1,%2,%3}, {%4,%5,%6,%7}, {%8,%9}, {%0,%1,%2,%3};"
        : "+f"(c[0]), "+f"(c[1]), "+f"(c[2]), "+f"(c[3])
        : "r"(a.x), "r"(a.y), "r"(a.z), "r"(a.w), "r"(b.x), "r"(b.y));
}
__device__ __forceinline__ long long ld_idx(const void* p, long long i, int is64) {
    return is64 ? ((const long long*)p)[i] : (long long)((const int*)p)[i];
}
// block-local dtype detect: int64 little-endian ids < 2^31 have all odd
// 32-bit words zero; random int32 ids cannot produce that pattern.
__device__ __forceinline__ void local_detect(const unsigned* ei, const unsigned* et,
                                             int* f0, int* f1) {
    __shared__ int s0, s1;
    if (threadIdx.x == 0) {
        unsigned a = 0, b = 0;
        for (int j = 1; j < 64; j += 2) { a |= ei[j]; b |= et[j]; }
        s0 = (a == 0) ? 1 : 0;
        s1 = (b == 0) ? 1 : 0;
    }
    __syncthreads();
    *f0 = s0; *f1 = s1;
}

// ========== launch 0: edge count + weight pack + scan-state reset ==========
__global__ void countw_kernel(const unsigned* __restrict__ ei,
                              const unsigned* __restrict__ et, int E, int EB,
                              const float* __restrict__ w1, const float* __restrict__ r1,
                              const float* __restrict__ w2, const float* __restrict__ r2) {
    int b = blockIdx.x;
    int tid = threadIdx.x;
    if (b < EB) {
        int f0, f1;
        local_detect(ei, et, &f0, &f1);
        if (b == 0) {
            for (int i = tid; i < NBLK; i += 256) g_tstat[i] = 0ULL;
            if (tid == 0) g_tilectr = 0;
        }
        int e = b * 256 + tid;
        if (e >= E) return;
        int dst = (int)ld_idx(ei, (long long)E + e, f0);
        int rel = (int)ld_idx(et, e, f1);
        atomicAdd(&g_cnt[rel * NN + dst], 1);
    } else {
        int b2 = b - EB;               // 0..17
        int l = b2 / NMAT, m = b2 % NMAT;
        const float* src = (l == 0) ? (m < RR ? w1 + (size_t)m * DD * DD : r1)
                                    : (m < RR ? w2 + (size_t)m * DD * DD : r2);
        float* dst = g_wt + (size_t)(l * NMAT + m) * DD * DD;
        for (int idx = tid; idx < DD * DD; idx += 256) {
            int k = idx >> 7, n = idx & 127;
            float v = to_tf32(src[idx]);
            int kc = k >> 3, nt = n >> 3;
            int lane = (n & 7) * 4 + (k & 3);
            int slot = (k >> 2) & 1;
            dst[((kc * 16 + nt) * 32 + lane) * 2 + slot] = v;
        }
    }
}

// ========== launch 1: single-pass exclusive scan (decoupled lookback) ==========
#define FLAG_AGG (1ULL << 62)
#define FLAG_PFX (2ULL << 62)
#define VAL_MASK ((1ULL << 62) - 1)

__global__ __launch_bounds__(512)
void scan_kernel(int E) {
    __shared__ int s[512];
    __shared__ int s_tile, s_base;
    int tid = threadIdx.x;
    if (tid == 0) s_tile = atomicAdd(&g_tilectr, 1);
    __syncthreads();
    int tile = s_tile;
    int idx = tile * 512 + tid;

    int v = 0;
    if (idx < NSEG) { v = g_cnt[idx]; g_cnt[idx] = 0; }
    s[tid] = v;
    __syncthreads();
#pragma unroll
    for (int o = 1; o < 512; o <<= 1) {
        int t = (tid >= o) ? s[tid - o] : 0;
        __syncthreads();
        s[tid] += t;
        __syncthreads();
    }
    int incl = s[tid];
    int total = s[511];

    if (tid == 0) {
        if (tile == 0) {
            atomicExch(&g_tstat[0], FLAG_PFX | (unsigned long long)total);
            s_base = 0;
        } else {
            atomicExch(&g_tstat[tile], FLAG_AGG | (unsigned long long)total);
            long long run = 0;
            int t = tile - 1;
            while (true) {
                unsigned long long st;
                do { st = atomicAdd(&g_tstat[t], 0ULL); } while ((st >> 62) == 0);
                run += (long long)(st & VAL_MASK);
                if ((st >> 62) == 2) break;
                t--;
            }
            atomicExch(&g_tstat[tile],
                       FLAG_PFX | (unsigned long long)(run + (long long)total));
            s_base = (int)run;
        }
    }
    __syncthreads();
    int base = s_base;
    if (idx < NSEG) {
        int o = base + incl - v;
        g_off[idx] = o;
        g_work[idx] = o;
    }
    if (tile == NBLK - 1 && tid == 0) g_off[NSEG] = E;
}

// ========== launch 2: scatter ==========
__global__ void scatter_kernel(const unsigned* __restrict__ ei,
                               const unsigned* __restrict__ et, int E) {
    int f0, f1;
    local_detect(ei, et, &f0, &f1);
    int e = blockIdx.x * blockDim.x + threadIdx.x;
    if (e >= E) return;
    int src = (int)ld_idx(ei, e, f0);
    int dst = (int)ld_idx(ei, (long long)E + e, f0);
    int rel = (int)ld_idx(et, e, f1);
    int pos = atomicAdd(&g_work[rel * NN + dst], 1);
    g_csrc[pos] = src;
}

// ========== launches 3,4: fused RGCN layer ==========
// 512 threads, 16 warps, 32x32 warp tiles -> ~60 regs/thread -> 2 CTAs/SM,
// 32 warps/SM. smem = A tile only (67.6 KB); B frags via LDG from L1/L2.
#define SM_TOTAL (128 * SA * 4)

#define FLUSH_ROW(rowloc)                                                          \
    do {                                                                           \
        int _b = __shfl_sync(0xffffffffu, offl, (rowloc));                         \
        int _e = __shfl_sync(0xffffffffu, offl, (rowloc) + 1);                     \
        float _sc = __fdividef(1.0f, (float)(_e - _b));                            \
        *(float4*)(At + (rowbase + (rowloc)) * SA + lane * 4) =                    \
            make_float4(to_tf32(acc.x * _sc), to_tf32(acc.y * _sc),                \
                        to_tf32(acc.z * _sc), to_tf32(acc.w * _sc));               \
    } while (0)

__global__ __launch_bounds__(512, 2)
void fused_layer(const float* __restrict__ Xopt, int layer,
                 const float* __restrict__ bias, float* __restrict__ dout) {
    extern __shared__ char smem[];
    float* At = (float*)smem;

    const float* X = Xopt ? Xopt : g_h;
    int tid = threadIdx.x;
    int lane = tid & 31, wid = tid >> 5;        // 16 warps
    int wm = wid & 3, wn = wid >> 2;            // 4x4 warps -> 32x32 tiles
    int n0 = blockIdx.x * 128;

    float accm[2][4][4];
#pragma unroll
    for (int i = 0; i < 2; i++)
#pragma unroll
        for (int j = 0; j < 4; j++)
#pragma unroll
            for (int q = 0; q < 4; q++) accm[i][j][q] = 0.f;

    for (int r = 0; r < NMAT; r++) {
        if (r < RR) {
            int rowbase = wid * 8;              // 8 rows per warp
            int offl = 0;
            {
                int node = n0 + rowbase + lane;
                if (node > NN) node = NN;
                if (lane < 9) offl = g_off[r * NN + node];
            }
#pragma unroll
            for (int i = 0; i < 8; i++)
                *(float4*)(At + (rowbase + i) * SA + lane * 4) =
                    make_float4(0.f, 0.f, 0.f, 0.f);

            int beg = __shfl_sync(0xffffffffu, offl, 0);
            int end = __shfl_sync(0xffffffffu, offl, 8);
            int nE = end - beg;

            int cur = 0, have = 0;
            int nxtb = __shfl_sync(0xffffffffu, offl, 1) - beg;
            float4 acc = make_float4(0.f, 0.f, 0.f, 0.f);

            for (int base = 0; base < nE; base += 32) {
                int m = min(32, nE - base);
                int sidx = 0;
                if (lane < m) sidx = g_csrc[beg + base + lane];

                float4 v0 = make_float4(0.f, 0.f, 0.f, 0.f), v1 = v0, v2 = v0;
                {
                    int s = __shfl_sync(0xffffffffu, sidx, 0);
                    v0 = *(const float4*)(X + (size_t)s * DD + lane * 4);
                    if (1 < m) {
                        s = __shfl_sync(0xffffffffu, sidx, 1);
                        v1 = *(const float4*)(X + (size_t)s * DD + lane * 4);
                    }
                    if (2 < m) {
                        s = __shfl_sync(0xffffffffu, sidx, 2);
                        v2 = *(const float4*)(X + (size_t)s * DD + lane * 4);
                    }
                }
                for (int j = 0; j < m; j++) {
                    float4 v = v0;
                    v0 = v1; v1 = v2;
                    if (j + 3 < m) {
                        int s = __shfl_sync(0xffffffffu, sidx, j + 3);
                        v2 = *(const float4*)(X + (size_t)s * DD + lane * 4);
                    }
                    int epos = base + j;
                    while (cur < 7 && epos >= nxtb) {
                        if (have) {
                            FLUSH_ROW(cur);
                            have = 0;
                            acc = make_float4(0.f, 0.f, 0.f, 0.f);
                        }
                        cur++;
                        nxtb = __shfl_sync(0xffffffffu, offl, cur + 1) - beg;
                    }
                    acc.x += v.x; acc.y += v.y; acc.z += v.z; acc.w += v.w;
                    have = 1;
                }
            }
            if (have) FLUSH_ROW(cur);
        } else {
            // root term: copy own rows (tf32-rounded); 512 thr x 8 float4 = tile
#pragma unroll
            for (int i = 0; i < 8; i++) {
                int row = tid >> 2;
                int q = (tid & 3) * 8 + i;      // float4 column index 0..31
                float4 v = make_float4(0.f, 0.f, 0.f, 0.f);
                if (n0 + row < NN)
                    v = *(const float4*)(X + (size_t)(n0 + row) * DD + q * 4);
                *(float4*)(At + row * SA + q * 4) =
                    make_float4(to_tf32(v.x), to_tf32(v.y), to_tf32(v.z), to_tf32(v.w));
            }
        }

        __syncthreads();   // At ready

        // 128x128x128 accumulate; B frags straight from L1/L2-resident g_wt
        const float* Bw = g_wt + (size_t)(layer * NMAT + r) * DD * DD;
#pragma unroll
        for (int kc = 0; kc < 16; kc++) {
            int c0 = kc * 8 + (lane & 3);
            uint4 aF[2];
            uint2 bF[4];
#pragma unroll
            for (int nf = 0; nf < 4; nf++)
                bF[nf] = *(const uint2*)(Bw + ((kc * 16 + wn * 4 + nf) * 32 + lane) * 2);
#pragma unroll
            for (int mf = 0; mf < 2; mf++) {
                int r0 = wm * 32 + mf * 16 + (lane >> 2);
                aF[mf].x = __float_as_uint(At[r0 * SA + c0]);
                aF[mf].y = __float_as_uint(At[(r0 + 8) * SA + c0]);
                aF[mf].z = __float_as_uint(At[r0 * SA + c0 + 4]);
                aF[mf].w = __float_as_uint(At[(r0 + 8) * SA + c0 + 4]);
            }
#pragma unroll
            for (int mf = 0; mf < 2; mf++)
#pragma unroll
                for (int nf = 0; nf < 4; nf++)
                    mma_tf32(accm[mf][nf], aF[mf], bF[nf]);
        }
        __syncthreads();   // protect At before next relation overwrites
    }

    // epilogue: bias + relu
    float* O = dout ? dout : g_h;
#pragma unroll
    for (int mf = 0; mf < 2; mf++) {
        int r0 = wm * 32 + mf * 16 + (lane >> 2);
#pragma unroll
        for (int nf = 0; nf < 4; nf++) {
            int col = wn * 32 + nf * 8 + 2 * (lane & 3);
#pragma unroll
            for (int h = 0; h < 2; h++) {
                int gr = n0 + r0 + h * 8;
                if (gr < NN) {
                    float v0 = fmaxf(accm[mf][nf][h * 2 + 0] + bias[col], 0.f);
                    float v1 = fmaxf(accm[mf][nf][h * 2 + 1] + bias[col + 1], 0.f);
                    *(float2*)(O + (size_t)gr * DD + col) = make_float2(v0, v1);
                }
            }
        }
    }
}

// =================================================================
extern "C" void kernel_launch(void* const* d_in, const int* in_sizes, int n_in,
                              void* d_out, int out_size) {
    const float* x     = (const float*)d_in[0];
    const unsigned* ei = (const unsigned*)d_in[1];
    const unsigned* et = (const unsigned*)d_in[2];
    const float* w1    = (const float*)d_in[3];
    const float* root1 = (const float*)d_in[4];
    const float* b1    = (const float*)d_in[5];
    const float* w2    = (const float*)d_in[6];
    const float* root2 = (const float*)d_in[7];
    const float* b2    = (const float*)d_in[8];
    float* out = (float*)d_out;

    int E = in_sizes[2];
    int EB = (E + 255) / 256;

    cudaFuncSetAttribute(fused_layer, cudaFuncAttributeMaxDynamicSharedMemorySize, SM_TOTAL);

    countw_kernel<<<EB + 2 * NMAT, 256>>>(ei, et, E, EB, w1, root1, w2, root2); // 0
    scan_kernel<<<NBLK, 512>>>(E);                                              // 1
    scatter_kernel<<<EB, 256>>>(ei, et, E);                                     // 2

    fused_layer<<<391, 512, SM_TOTAL>>>(x, 0, b1, nullptr);     // 3 <- ncu capture
    fused_layer<<<391, 512, SM_TOTAL>>>(nullptr, 1, b2, out);   // 4
}

// round 15
// speedup vs baseline: 1.5824x; 1.1005x over previous
#include <cuda_runtime.h>
#include <cstdint>

#define NN 50000
#define DD 128
#define RR 8
#define NMAT 9
#define NSEG (RR * NN)             // 400000 segments: seg = rel*NN + dst
#define NBLK ((NSEG + 511) / 512)  // 782 scan tiles
#define SA 132                     // A-tile row stride (conflict-free frag loads)
#define TM 64                      // fused-layer tile rows

// ---- static device scratch ----
__device__ float g_h[(size_t)NN * DD];            // hidden layer (25.6 MB)
__device__ float g_wt[2 * NMAT * DD * DD];        // frag-packed tf32 weights
__device__ int   g_cnt[NSEG];                     // zero-init; re-zeroed by scan
__device__ int   g_off[NSEG + 1];
__device__ int   g_work[NSEG];
__device__ int   g_csrc[600000 + 64];             // CSR src lists
__device__ unsigned long long g_tstat[NBLK];      // lookback scan tile status
__device__ int   g_tilectr;

// ================= helpers =================
__device__ __forceinline__ float to_tf32(float x) {
    float r;
    asm("cvt.rna.tf32.f32 %0, %1;" : "=f"(r) : "f"(x));
    return r;
}
__device__ __forceinline__ void mma_tf32(float* c, const uint4 a, const uint2 b) {
    asm volatile(
        "mma.sync.aligned.m16n8k8.row.col.f32.tf32.tf32.f32 "
        "{%0,%1,%2,%3}, {%4,%5,%6,%7}, {%8,%9}, {%0,%1,%2,%3};"
        : "+f"(c[0]), "+f"(c[1]), "+f"(c[2]), "+f"(c[3])
        : "r"(a.x), "r"(a.y), "r"(a.z), "r"(a.w), "r"(b.x), "r"(b.y));
}
__device__ __forceinline__ long long ld_idx(const void* p, long long i, int is64) {
    return is64 ? ((const long long*)p)[i] : (long long)((const int*)p)[i];
}
__device__ __forceinline__ void local_detect(const unsigned* ei, const unsigned* et,
                                             int* f0, int* f1) {
    __shared__ int s0, s1;
    if (threadIdx.x == 0) {
        unsigned a = 0, b = 0;
        for (int j = 1; j < 64; j += 2) { a |= ei[j]; b |= et[j]; }
        s0 = (a == 0) ? 1 : 0;
        s1 = (b == 0) ? 1 : 0;
    }
    __syncthreads();
    *f0 = s0; *f1 = s1;
}

#define BAR_SYNC(id)   asm volatile("bar.sync %0, 512;"   :: "r"(id) : "memory")
#define BAR_ARRIVE(id) asm volatile("bar.arrive %0, 512;" :: "r"(id) : "memory")
#define MEMBAR_CTA()   asm volatile("membar.cta;" ::: "memory")

// ========== launch 0: edge count + weight pack + scan-state reset ==========
__global__ void countw_kernel(const unsigned* __restrict__ ei,
                              const unsigned* __restrict__ et, int E, int EB,
                              const float* __restrict__ w1, const float* __restrict__ r1,
                              const float* __restrict__ w2, const float* __restrict__ r2) {
    int b = blockIdx.x;
    int tid = threadIdx.x;
    if (b < EB) {
        int f0, f1;
        local_detect(ei, et, &f0, &f1);
        if (b == 0) {
            for (int i = tid; i < NBLK; i += 256) g_tstat[i] = 0ULL;
            if (tid == 0) g_tilectr = 0;
        }
        int e = b * 256 + tid;
        if (e >= E) return;
        int dst = (int)ld_idx(ei, (long long)E + e, f0);
        int rel = (int)ld_idx(et, e, f1);
        atomicAdd(&g_cnt[rel * NN + dst], 1);
    } else {
        int b2 = b - EB;               // 0..17
        int l = b2 / NMAT, m = b2 % NMAT;
        const float* src = (l == 0) ? (m < RR ? w1 + (size_t)m * DD * DD : r1)
                                    : (m < RR ? w2 + (size_t)m * DD * DD : r2);
        float* dst = g_wt + (size_t)(l * NMAT + m) * DD * DD;
        for (int idx = tid; idx < DD * DD; idx += 256) {
            int k = idx >> 7, n = idx & 127;
            float v = to_tf32(src[idx]);
            int kc = k >> 3, nt = n >> 3;
            int lane = (n & 7) * 4 + (k & 3);
            int slot = (k >> 2) & 1;
            dst[((kc * 16 + nt) * 32 + lane) * 2 + slot] = v;
        }
    }
}

// ========== launch 1: single-pass exclusive scan (decoupled lookback) ==========
#define FLAG_AGG (1ULL << 62)
#define FLAG_PFX (2ULL << 62)
#define VAL_MASK ((1ULL << 62) - 1)

__global__ __launch_bounds__(512)
void scan_kernel(int E) {
    __shared__ int s[512];
    __shared__ int s_tile, s_base;
    int tid = threadIdx.x;
    if (tid == 0) s_tile = atomicAdd(&g_tilectr, 1);
    __syncthreads();
    int tile = s_tile;
    int idx = tile * 512 + tid;

    int v = 0;
    if (idx < NSEG) { v = g_cnt[idx]; g_cnt[idx] = 0; }
    s[tid] = v;
    __syncthreads();
#pragma unroll
    for (int o = 1; o < 512; o <<= 1) {
        int t = (tid >= o) ? s[tid - o] : 0;
        __syncthreads();
        s[tid] += t;
        __syncthreads();
    }
    int incl = s[tid];
    int total = s[511];

    if (tid == 0) {
        if (tile == 0) {
            atomicExch(&g_tstat[0], FLAG_PFX | (unsigned long long)total);
            s_base = 0;
        } else {
            atomicExch(&g_tstat[tile], FLAG_AGG | (unsigned long long)total);
            long long run = 0;
            int t = tile - 1;
            while (true) {
                unsigned long long st;
                do { st = atomicAdd(&g_tstat[t], 0ULL); } while ((st >> 62) == 0);
                run += (long long)(st & VAL_MASK);
                if ((st >> 62) == 2) break;
                t--;
            }
            atomicExch(&g_tstat[tile],
                       FLAG_PFX | (unsigned long long)(run + (long long)total));
            s_base = (int)run;
        }
    }
    __syncthreads();
    int base = s_base;
    if (idx < NSEG) {
        int o = base + incl - v;
        g_off[idx] = o;
        g_work[idx] = o;
    }
    if (tile == NBLK - 1 && tid == 0) g_off[NSEG] = E;
}

// ========== launch 2: scatter ==========
__global__ void scatter_kernel(const unsigned* __restrict__ ei,
                               const unsigned* __restrict__ et, int E) {
    int f0, f1;
    local_detect(ei, et, &f0, &f1);
    int e = blockIdx.x * blockDim.x + threadIdx.x;
    if (e >= E) return;
    int src = (int)ld_idx(ei, e, f0);
    int dst = (int)ld_idx(ei, (long long)E + e, f0);
    int rel = (int)ld_idx(et, e, f1);
    int pos = atomicAdd(&g_work[rel * NN + dst], 1);
    g_csrc[pos] = src;
}

// ========== launches 3,4: fused RGCN layer, producer/consumer ==========
// 64-row tiles, grid 782. Warps 0-7 gather relation r into buf[r&1];
// warps 8-15 MMA from the other buffer. Named-barrier ping-pong.
// smem = 2 x (64 x SA) floats = 67.6 KB -> 2 CTAs/SM.
#define SM_TOTAL (2 * TM * SA * 4)

#define FLUSH_ROW(rowloc)                                                          \
    do {                                                                           \
        int _b = __shfl_sync(0xffffffffu, offl, (rowloc));                         \
        int _e = __shfl_sync(0xffffffffu, offl, (rowloc) + 1);                     \
        float _sc = __fdividef(1.0f, (float)(_e - _b));                            \
        *(float4*)(Abuf + (rowbase + (rowloc)) * SA + lane * 4) =                  \
            make_float4(to_tf32(acc.x * _sc), to_tf32(acc.y * _sc),                \
                        to_tf32(acc.z * _sc), to_tf32(acc.w * _sc));               \
    } while (0)

__global__ __launch_bounds__(512, 2)
void fused_layer(const float* __restrict__ Xopt, int layer,
                 const float* __restrict__ bias, float* __restrict__ dout) {
    extern __shared__ char smem[];
    float* At = (float*)smem;

    const float* X = Xopt ? Xopt : g_h;
    int tid = threadIdx.x;
    int lane = tid & 31, wid = tid >> 5;
    int n0 = blockIdx.x * TM;

    if (wid < 8) {
        // ---------------- producer: gather ----------------
        for (int r = 0; r < NMAT; r++) {
            int b = r & 1;
            float* Abuf = At + b * TM * SA;
            if (r >= 2) BAR_SYNC(3 + b);           // wait buffer free

            if (r < RR) {
                int rowbase = wid * 8;             // 8 rows per producer warp
                int offl = 0;
                {
                    int node = n0 + rowbase + lane;
                    if (node > NN) node = NN;
                    if (lane < 9) offl = g_off[r * NN + node];
                }
#pragma unroll
                for (int i = 0; i < 8; i++)
                    *(float4*)(Abuf + (rowbase + i) * SA + lane * 4) =
                        make_float4(0.f, 0.f, 0.f, 0.f);

                int beg = __shfl_sync(0xffffffffu, offl, 0);
                int end = __shfl_sync(0xffffffffu, offl, 8);
                int nE = end - beg;

                int cur = 0, have = 0;
                int nxtb = __shfl_sync(0xffffffffu, offl, 1) - beg;
                float4 acc = make_float4(0.f, 0.f, 0.f, 0.f);

                for (int base = 0; base < nE; base += 32) {
                    int m = min(32, nE - base);
                    int sidx = 0;
                    if (lane < m) sidx = g_csrc[beg + base + lane];

                    float4 v0 = make_float4(0.f, 0.f, 0.f, 0.f), v1 = v0, v2 = v0;
                    {
                        int s = __shfl_sync(0xffffffffu, sidx, 0);
                        v0 = *(const float4*)(X + (size_t)s * DD + lane * 4);
                        if (1 < m) {
                            s = __shfl_sync(0xffffffffu, sidx, 1);
                            v1 = *(const float4*)(X + (size_t)s * DD + lane * 4);
                        }
                        if (2 < m) {
                            s = __shfl_sync(0xffffffffu, sidx, 2);
                            v2 = *(const float4*)(X + (size_t)s * DD + lane * 4);
                        }
                    }
                    for (int j = 0; j < m; j++) {
                        float4 v = v0;
                        v0 = v1; v1 = v2;
                        if (j + 3 < m) {
                            int s = __shfl_sync(0xffffffffu, sidx, j + 3);
                            v2 = *(const float4*)(X + (size_t)s * DD + lane * 4);
                        }
                        int epos = base + j;
                        while (cur < 7 && epos >= nxtb) {
                            if (have) {
                                FLUSH_ROW(cur);
                                have = 0;
                                acc = make_float4(0.f, 0.f, 0.f, 0.f);
                            }
                            cur++;
                            nxtb = __shfl_sync(0xffffffffu, offl, cur + 1) - beg;
                        }
                        acc.x += v.x; acc.y += v.y; acc.z += v.z; acc.w += v.w;
                        have = 1;
                    }
                }
                if (have) FLUSH_ROW(cur);
            } else {
                // root: 256 producer threads copy 64 rows (tf32-rounded)
#pragma unroll
                for (int i = 0; i < 8; i++) {
                    int row = tid >> 2;              // 0..63
                    int q = (tid & 3) * 8 + i;       // float4 col 0..31
                    float4 v = make_float4(0.f, 0.f, 0.f, 0.f);
                    if (n0 + row < NN)
                        v = *(const float4*)(X + (size_t)(n0 + row) * DD + q * 4);
                    *(float4*)(Abuf + row * SA + q * 4) =
                        make_float4(to_tf32(v.x), to_tf32(v.y), to_tf32(v.z), to_tf32(v.w));
                }
            }
            MEMBAR_CTA();
            BAR_ARRIVE(1 + b);                      // signal full
        }
    } else {
        // ---------------- consumer: MMA + epilogue ----------------
        int cwid = wid - 8;
        int wm = cwid >> 2, wn = cwid & 3;          // 2x4 -> 32x32 warp tiles

        float accm[2][4][4];
#pragma unroll
        for (int i = 0; i < 2; i++)
#pragma unroll
            for (int j = 0; j < 4; j++)
#pragma unroll
                for (int q = 0; q < 4; q++) accm[i][j][q] = 0.f;

        for (int r = 0; r < NMAT; r++) {
            int b = r & 1;
            const float* Abuf = At + b * TM * SA;
            BAR_SYNC(1 + b);                        // wait buffer full

            const float* Bw = g_wt + (size_t)(layer * NMAT + r) * DD * DD;
#pragma unroll
            for (int kc = 0; kc < 16; kc++) {
                int c0 = kc * 8 + (lane & 3);
                uint4 aF[2];
                uint2 bF[4];
#pragma unroll
                for (int nf = 0; nf < 4; nf++)
                    bF[nf] = *(const uint2*)(Bw + ((kc * 16 + wn * 4 + nf) * 32 + lane) * 2);
#pragma unroll
                for (int mf = 0; mf < 2; mf++) {
                    int r0 = wm * 32 + mf * 16 + (lane >> 2);
                    aF[mf].x = __float_as_uint(Abuf[r0 * SA + c0]);
                    aF[mf].y = __float_as_uint(Abuf[(r0 + 8) * SA + c0]);
                    aF[mf].z = __float_as_uint(Abuf[r0 * SA + c0 + 4]);
                    aF[mf].w = __float_as_uint(Abuf[(r0 + 8) * SA + c0 + 4]);
                }
#pragma unroll
                for (int mf = 0; mf < 2; mf++)
#pragma unroll
                    for (int nf = 0; nf < 4; nf++)
                        mma_tf32(accm[mf][nf], aF[mf], bF[nf]);
            }
            MEMBAR_CTA();
            BAR_ARRIVE(3 + b);                      // signal empty
        }

        // epilogue: bias + relu
        float* O = dout ? dout : g_h;
#pragma unroll
        for (int mf = 0; mf < 2; mf++) {
            int r0 = wm * 32 + mf * 16 + (lane >> 2);
#pragma unroll
            for (int nf = 0; nf < 4; nf++) {
                int col = wn * 32 + nf * 8 + 2 * (lane & 3);
#pragma unroll
                for (int h = 0; h < 2; h++) {
                    int gr = n0 + r0 + h * 8;
                    if (gr < NN) {
                        float v0 = fmaxf(accm[mf][nf][h * 2 + 0] + bias[col], 0.f);
                        float v1 = fmaxf(accm[mf][nf][h * 2 + 1] + bias[col + 1], 0.f);
                        *(float2*)(O + (size_t)gr * DD + col) = make_float2(v0, v1);
                    }
                }
            }
        }
    }
}

// =================================================================
extern "C" void kernel_launch(void* const* d_in, const int* in_sizes, int n_in,
                              void* d_out, int out_size) {
    const float* x     = (const float*)d_in[0];
    const unsigned* ei = (const unsigned*)d_in[1];
    const unsigned* et = (const unsigned*)d_in[2];
    const float* w1    = (const float*)d_in[3];
    const float* root1 = (const float*)d_in[4];
    const float* b1    = (const float*)d_in[5];
    const float* w2    = (const float*)d_in[6];
    const float* root2 = (const float*)d_in[7];
    const float* b2    = (const float*)d_in[8];
    float* out = (float*)d_out;

    int E = in_sizes[2];
    int EB = (E + 255) / 256;
    int NT = (NN + TM - 1) / TM;   // 782 tiles

    cudaFuncSetAttribute(fused_layer, cudaFuncAttributeMaxDynamicSharedMemorySize, SM_TOTAL);

    countw_kernel<<<EB + 2 * NMAT, 256>>>(ei, et, E, EB, w1, root1, w2, root2); // 0
    scan_kernel<<<NBLK, 512>>>(E);                                              // 1
    scatter_kernel<<<EB, 256>>>(ei, et, E);                                     // 2

    fused_layer<<<NT, 512, SM_TOTAL>>>(x, 0, b1, nullptr);      // 3 <- ncu capture
    fused_layer<<<NT, 512, SM_TOTAL>>>(nullptr, 1, b2, out);    // 4
}